// round 3
// baseline (speedup 1.0000x reference)
#include <cuda_runtime.h>

#define N_NODES 50000
#define N_EDGES 800000
#define IN_CH   128
#define HID     128
#define OUT_CH  64

// ---------------- scratch (device globals; referenced directly by symbol) --
__device__ float g_h1[(size_t)N_NODES * HID];     // x @ W1
__device__ float g_a1[(size_t)N_NODES * HID];     // propagated layer-1 activations
__device__ float g_h2[(size_t)N_NODES * OUT_CH];  // (a1+b1) @ W2
__device__ int   g_deg[N_NODES];
__device__ float g_dinv[N_NODES];

// ---------------- degree / norm -------------------------------------------
__global__ void init_deg_kernel() {
    int i = blockIdx.x * blockDim.x + threadIdx.x;
    if (i < N_NODES) g_deg[i] = 1;  // self-loop
}

__global__ void count_deg_kernel(const int* __restrict__ dst) {
    int e = blockIdx.x * blockDim.x + threadIdx.x;
    if (e < N_EDGES) atomicAdd(&g_deg[dst[e]], 1);
}

__global__ void dinv_kernel() {
    int i = blockIdx.x * blockDim.x + threadIdx.x;
    if (i < N_NODES) g_dinv[i] = rsqrtf((float)g_deg[i]);
}

// ---------------- dense GEMM: Y[n][j] = sum_k (X[n][k]+bias_in[k]) * W[k][j]
// Block: OUT threads (one output column each), NB rows per block.
// SEL: 0 -> Y = g_h1, 1 -> Y = g_h2 (device-global outputs, no host symbols).
template <int IN, int OUT, int NB, bool HASB, int SEL, bool XGLOBAL>
__global__ void gemm_kernel(const float* __restrict__ Xin,
                            const float* __restrict__ W,
                            const float* __restrict__ bias_in) {
    __shared__ float sW[32][OUT];
    __shared__ float sX[NB][32];
    const float* X = XGLOBAL ? g_a1 : Xin;
    float*       Y = (SEL == 0) ? g_h1 : g_h2;
    const int j    = threadIdx.x;           // output column
    const int row0 = blockIdx.x * NB;

    float acc[NB];
#pragma unroll
    for (int n = 0; n < NB; n++) acc[n] = 0.0f;

    for (int kc = 0; kc < IN; kc += 32) {
#pragma unroll
        for (int r = 0; r < 32; r++)
            sW[r][j] = W[(kc + r) * OUT + j];
        for (int idx = j; idx < NB * 32; idx += OUT) {
            int n = idx >> 5, k = idx & 31;
            float v = X[(size_t)(row0 + n) * IN + kc + k];
            if (HASB) v += bias_in[kc + k];
            sX[n][k] = v;
        }
        __syncthreads();
#pragma unroll
        for (int k = 0; k < 32; k++) {
            float w = sW[k][j];
#pragma unroll
            for (int n = 0; n < NB; n++) acc[n] += sX[n][k] * w;
        }
        __syncthreads();
    }
#pragma unroll
    for (int n = 0; n < NB; n++)
        Y[(size_t)(row0 + n) * OUT + j] = acc[n];
}

// ---------------- self-loop init:  A[i][f] = H[i][f]*dinv[i]^2 (+ bias[f]) -
// SEL: 0 -> H=g_h1, A=g_a1; 1 -> H=g_h2, A=out (passed in).
template <int F, bool HASB, int SEL>
__global__ void selfloop_kernel(const float* __restrict__ bias,
                                float* __restrict__ Aout) {
    const float* H = (SEL == 0) ? g_h1 : g_h2;
    float*       A = (SEL == 0) ? g_a1 : Aout;
    int t = blockIdx.x * blockDim.x + threadIdx.x;
    if (t >= N_NODES * F) return;
    int node = t / F;
    int f    = t - node * F;
    float di = g_dinv[node];
    float v  = H[t] * di * di;
    if (HASB) v += bias[f];
    A[t] = v;
}

// ---------------- edge scatter-add: A[dst] += H[src] * dinv[src]*dinv[dst] -
// One float4 (4 features) per thread; F/4 lanes per edge.
template <int F, int SEL>
__global__ void scatter_kernel(const int* __restrict__ src,
                               const int* __restrict__ dst,
                               float* __restrict__ Aout) {
    const float* H = (SEL == 0) ? g_h1 : g_h2;
    float*       A = (SEL == 0) ? g_a1 : Aout;
    const int LPE = F / 4;
    long long t = (long long)blockIdx.x * blockDim.x + threadIdx.x;
    long long e = t / LPE;
    int       l = (int)(t - e * LPE);
    if (e >= N_EDGES) return;
    int s = __ldg(&src[e]);
    int d = __ldg(&dst[e]);
    float nrm = g_dinv[s] * g_dinv[d];
    float4 v = *(const float4*)(H + (size_t)s * F + l * 4);
    float* outp = A + (size_t)d * F + l * 4;
    atomicAdd(outp + 0, v.x * nrm);
    atomicAdd(outp + 1, v.y * nrm);
    atomicAdd(outp + 2, v.z * nrm);
    atomicAdd(outp + 3, v.w * nrm);
}

// ---------------- launch ---------------------------------------------------
extern "C" void kernel_launch(void* const* d_in, const int* in_sizes, int n_in,
                              void* d_out, int out_size) {
    const float* x   = (const float*)d_in[0];
    const int*   ei  = (const int*)d_in[1];   // int32! JAX demotes int64 by default
    const float* W1  = (const float*)d_in[2];
    const float* b1  = (const float*)d_in[3];
    const float* W2  = (const float*)d_in[4];
    const float* b2  = (const float*)d_in[5];
    float*       out = (float*)d_out;

    const int* e_src = ei;            // edge_index[0]
    const int* e_dst = ei + N_EDGES;  // edge_index[1]

    const int T = 256;

    // degrees + norms
    init_deg_kernel<<<(N_NODES + T - 1) / T, T>>>();
    count_deg_kernel<<<(N_EDGES + T - 1) / T, T>>>(e_dst);
    dinv_kernel<<<(N_NODES + T - 1) / T, T>>>();

    // layer 1: g_h1 = x @ W1
    gemm_kernel<IN_CH, HID, 8, false, 0, false><<<N_NODES / 8, HID>>>(x, W1, nullptr);
    // g_a1 = dinv^2 * g_h1 (self-loop term), then scatter-add edges
    selfloop_kernel<HID, false, 0>
        <<<(N_NODES * HID + T - 1) / T, T>>>(nullptr, nullptr);
    {
        long long nt = (long long)N_EDGES * (HID / 4);
        scatter_kernel<HID, 0><<<(unsigned)((nt + T - 1) / T), T>>>(e_src, e_dst, nullptr);
    }

    // layer 2: g_h2 = (g_a1 + b1) @ W2   (bias b1 folded into GEMM input)
    gemm_kernel<HID, OUT_CH, 8, true, 1, true><<<N_NODES / 8, OUT_CH>>>(nullptr, W2, b1);
    // out = dinv^2 * g_h2 + b2, then scatter-add edges
    selfloop_kernel<OUT_CH, true, 1>
        <<<(N_NODES * OUT_CH + T - 1) / T, T>>>(b2, out);
    {
        long long nt = (long long)N_EDGES * (OUT_CH / 4);
        scatter_kernel<OUT_CH, 1><<<(unsigned)((nt + T - 1) / T), T>>>(e_src, e_dst, out);
    }
}

// round 4
// speedup vs baseline: 2.7951x; 2.7951x over previous
#include <cuda_runtime.h>

#define N_NODES 50000
#define N_EDGES 800000
#define IN_CH   128
#define HID     128
#define OUT_CH  64
#define NCHUNK  ((N_NODES + 255) / 256)   // 196

// ---------------- device-global scratch ------------------------------------
__device__ float g_h1[(size_t)N_NODES * HID];
__device__ float g_a1[(size_t)N_NODES * HID];
__device__ float g_h2[(size_t)N_NODES * OUT_CH];
__device__ int   g_deg[N_NODES];
__device__ float g_dinv[N_NODES];
__device__ int   g_row_start[N_NODES + 1];
__device__ int   g_cnt[N_NODES];
__device__ int   g_csr_src[N_EDGES];
__device__ float g_csr_nrm[N_EDGES];
__device__ int   g_bsum[NCHUNK];
__device__ int   g_boff[NCHUNK];

// ---------------- degree / norm --------------------------------------------
__global__ void init_deg_kernel() {
    int i = blockIdx.x * blockDim.x + threadIdx.x;
    if (i < N_NODES) { g_deg[i] = 1; g_cnt[i] = 0; }  // self-loop counts once
}

__global__ void count_deg_kernel(const int* __restrict__ dst) {
    int e = blockIdx.x * blockDim.x + threadIdx.x;
    if (e < N_EDGES) atomicAdd(&g_deg[dst[e]], 1);
}

__global__ void dinv_kernel() {
    int i = blockIdx.x * blockDim.x + threadIdx.x;
    if (i < N_NODES) g_dinv[i] = rsqrtf((float)g_deg[i]);
}

// ---------------- 3-kernel exclusive scan of edge in-degree (deg-1) --------
__global__ void scan1_kernel() {
    __shared__ int s[256];
    int i = blockIdx.x * 256 + threadIdx.x;
    int val = (i < N_NODES) ? (g_deg[i] - 1) : 0;
    s[threadIdx.x] = val;
    __syncthreads();
#pragma unroll
    for (int off = 1; off < 256; off <<= 1) {
        int t = (threadIdx.x >= off) ? s[threadIdx.x - off] : 0;
        __syncthreads();
        s[threadIdx.x] += t;
        __syncthreads();
    }
    if (i < N_NODES) g_row_start[i] = s[threadIdx.x] - val;  // exclusive
    if (threadIdx.x == 255) g_bsum[blockIdx.x] = s[255];
}

__global__ void scan2_kernel() {
    __shared__ int s[256];
    int t = threadIdx.x;
    int val = (t < NCHUNK) ? g_bsum[t] : 0;
    s[t] = val;
    __syncthreads();
#pragma unroll
    for (int off = 1; off < 256; off <<= 1) {
        int v = (t >= off) ? s[t - off] : 0;
        __syncthreads();
        s[t] += v;
        __syncthreads();
    }
    if (t < NCHUNK) g_boff[t] = s[t] - val;  // exclusive
}

__global__ void scan3_kernel() {
    int i = blockIdx.x * 256 + threadIdx.x;
    if (i < N_NODES) g_row_start[i] += g_boff[blockIdx.x];
    if (i == 0) g_row_start[N_NODES] = N_EDGES;
}

// ---------------- CSR placement (counting sort by dst) ---------------------
__global__ void place_kernel(const int* __restrict__ src,
                             const int* __restrict__ dst) {
    int e = blockIdx.x * blockDim.x + threadIdx.x;
    if (e >= N_EDGES) return;
    int s = src[e], d = dst[e];
    int pos = g_row_start[d] + atomicAdd(&g_cnt[d], 1);
    g_csr_src[pos] = s;
    g_csr_nrm[pos] = g_dinv[s] * g_dinv[d];
}

// ---------------- register-blocked SGEMM -----------------------------------
// Y[BM=128 x OUT] per block, BK=8, 8x8 micro-tile/thread.
// HASB folds bias into the X read (layer-2 input = a1 + b1).
template <int IN, int OUT, bool HASB, int SEL, bool XGLOBAL>
__global__ void sgemm_kernel(const float* __restrict__ Xin,
                             const float* __restrict__ W,
                             const float* __restrict__ bias_in) {
    constexpr int BM = 128, BK = 8, BN = OUT;
    constexpr int TX = BN / 8, NT = TX * 16;
    __shared__ float sA[BK][BM];
    __shared__ float sB[BK][BN];
    const float* X = XGLOBAL ? g_a1 : Xin;
    float*       Y = (SEL == 0) ? g_h1 : g_h2;
    const int tid = threadIdx.x;
    const int tx = tid % TX, ty = tid / TX;
    const int row0 = blockIdx.x * BM;

    float acc[8][8] = {};
    for (int kc = 0; kc < IN; kc += BK) {
        // A tile: BM*BK = 1024 floats = 256 float4
#pragma unroll
        for (int v = 0; v < 256 / NT; v++) {
            int a = tid + v * NT;
            int row = a >> 1, kq = (a & 1) * 4;
            float4 val = make_float4(0.f, 0.f, 0.f, 0.f);
            if (row0 + row < N_NODES)
                val = *(const float4*)(X + (size_t)(row0 + row) * IN + kc + kq);
            if (HASB) {
                val.x += bias_in[kc + kq];     val.y += bias_in[kc + kq + 1];
                val.z += bias_in[kc + kq + 2]; val.w += bias_in[kc + kq + 3];
            }
            sA[kq + 0][row] = val.x; sA[kq + 1][row] = val.y;
            sA[kq + 2][row] = val.z; sA[kq + 3][row] = val.w;
        }
        // B tile: BK*BN floats = 2*OUT float4 == NT
        {
            int k = tid / (BN / 4), c4 = tid % (BN / 4);
            *(float4*)&sB[k][c4 * 4] =
                *(const float4*)(W + (size_t)(kc + k) * OUT + c4 * 4);
        }
        __syncthreads();
#pragma unroll
        for (int k = 0; k < BK; k++) {
            float ra[8], rb[8];
#pragma unroll
            for (int i = 0; i < 8; i++) ra[i] = sA[k][ty * 8 + i];
#pragma unroll
            for (int j = 0; j < 8; j++) rb[j] = sB[k][tx * 8 + j];
#pragma unroll
            for (int i = 0; i < 8; i++)
#pragma unroll
                for (int j = 0; j < 8; j++) acc[i][j] += ra[i] * rb[j];
        }
        __syncthreads();
    }
#pragma unroll
    for (int i = 0; i < 8; i++) {
        int row = row0 + ty * 8 + i;
        if (row < N_NODES) {
#pragma unroll
            for (int j = 0; j < 8; j += 4) {
                float4 v = make_float4(acc[i][j], acc[i][j + 1],
                                       acc[i][j + 2], acc[i][j + 3]);
                *(float4*)(Y + (size_t)row * OUT + tx * 8 + j) = v;
            }
        }
    }
}

// ---------------- CSR gather-reduce ----------------------------------------
// One F/4-lane group per node; float4 per lane; self term folded in.
template <int F, int SEL>
__global__ void gather_kernel(const float* __restrict__ bias,
                              float* __restrict__ Aout) {
    constexpr int TPN = F / 4;
    const float* H = (SEL == 0) ? g_h1 : g_h2;
    float*       A = (SEL == 0) ? g_a1 : Aout;
    int g = blockIdx.x * blockDim.x + threadIdx.x;
    int node = g / TPN;
    int lane = g % TPN;
    if (node >= N_NODES) return;
    int l4 = lane * 4;

    float di = g_dinv[node];
    float sc = di * di;
    float4 hv = *(const float4*)(H + (size_t)node * F + l4);
    float4 acc = make_float4(hv.x * sc, hv.y * sc, hv.z * sc, hv.w * sc);

    int k  = g_row_start[node];
    int re = g_row_start[node + 1];
    if (k < re) {
        int s = g_csr_src[k]; float nm = g_csr_nrm[k];
        while (++k < re) {           // software-pipelined index prefetch
            int s2 = g_csr_src[k]; float nm2 = g_csr_nrm[k];
            float4 v = *(const float4*)(H + (size_t)s * F + l4);
            acc.x += v.x * nm; acc.y += v.y * nm;
            acc.z += v.z * nm; acc.w += v.w * nm;
            s = s2; nm = nm2;
        }
        float4 v = *(const float4*)(H + (size_t)s * F + l4);
        acc.x += v.x * nm; acc.y += v.y * nm;
        acc.z += v.z * nm; acc.w += v.w * nm;
    }
    if (SEL == 1) {
        acc.x += bias[l4];     acc.y += bias[l4 + 1];
        acc.z += bias[l4 + 2]; acc.w += bias[l4 + 3];
    }
    *(float4*)(A + (size_t)node * F + l4) = acc;
}

// ---------------- launch ---------------------------------------------------
extern "C" void kernel_launch(void* const* d_in, const int* in_sizes, int n_in,
                              void* d_out, int out_size) {
    const float* x   = (const float*)d_in[0];
    const int*   ei  = (const int*)d_in[1];   // int32 (JAX demotes int64)
    const float* W1  = (const float*)d_in[2];
    const float* b1  = (const float*)d_in[3];
    const float* W2  = (const float*)d_in[4];
    const float* b2  = (const float*)d_in[5];
    float*       out = (float*)d_out;

    const int* e_src = ei;
    const int* e_dst = ei + N_EDGES;
    const int  T = 256;

    // degrees, norms, CSR build
    init_deg_kernel<<<(N_NODES + T - 1) / T, T>>>();
    count_deg_kernel<<<(N_EDGES + T - 1) / T, T>>>(e_dst);
    dinv_kernel<<<(N_NODES + T - 1) / T, T>>>();
    scan1_kernel<<<NCHUNK, 256>>>();
    scan2_kernel<<<1, 256>>>();
    scan3_kernel<<<NCHUNK, 256>>>();
    place_kernel<<<(N_EDGES + T - 1) / T, T>>>(e_src, e_dst);

    // layer 1
    sgemm_kernel<IN_CH, HID, false, 0, false>
        <<<(N_NODES + 127) / 128, (HID / 8) * 16>>>(x, W1, nullptr);
    gather_kernel<HID, 0>
        <<<(N_NODES * (HID / 4) + T - 1) / T, T>>>(nullptr, nullptr);

    // layer 2 (b1 folded into GEMM input, b2 added in gather epilogue)
    sgemm_kernel<HID, OUT_CH, true, 1, true>
        <<<(N_NODES + 127) / 128, (OUT_CH / 8) * 16>>>(nullptr, W2, b1);
    gather_kernel<OUT_CH, 1>
        <<<(N_NODES * (OUT_CH / 4) + T - 1) / T, T>>>(b2, out);
}

// round 5
// speedup vs baseline: 3.0648x; 1.0965x over previous
#include <cuda_runtime.h>

#define N_NODES 50000
#define N_EDGES 800000
#define IN_CH   128
#define HID     128
#define OUT_CH  64
#define NCHUNK  ((N_NODES + 255) / 256)   // 196

// ---------------- device-global scratch ------------------------------------
__device__ float g_h1[(size_t)N_NODES * HID];
__device__ float g_a1[(size_t)N_NODES * HID];
__device__ float g_h2[(size_t)N_NODES * OUT_CH];
__device__ int   g_deg[N_NODES];
__device__ float g_dinv[N_NODES];
__device__ int   g_row_start[N_NODES + 1];
__device__ int   g_cnt[N_NODES];
__device__ int   g_csr_src[N_EDGES];
__device__ float g_csr_nrm[N_EDGES];
__device__ int   g_bsum[NCHUNK];
__device__ int   g_boff[NCHUNK];

// ---------------- degree ----------------------------------------------------
__global__ void init_deg_kernel() {
    int i = blockIdx.x * blockDim.x + threadIdx.x;
    if (i < N_NODES) { g_deg[i] = 1; g_cnt[i] = 0; }  // self-loop counts once
}

__global__ void count_deg_kernel(const int* __restrict__ dst) {
    int e = blockIdx.x * blockDim.x + threadIdx.x;
    if (e < N_EDGES) atomicAdd(&g_deg[dst[e]], 1);
}

// ---------------- 3-kernel exclusive scan of edge in-degree (deg-1) --------
__global__ void scan1_kernel() {
    __shared__ int s[256];
    int i = blockIdx.x * 256 + threadIdx.x;
    int val = (i < N_NODES) ? (g_deg[i] - 1) : 0;
    s[threadIdx.x] = val;
    __syncthreads();
#pragma unroll
    for (int off = 1; off < 256; off <<= 1) {
        int t = (threadIdx.x >= off) ? s[threadIdx.x - off] : 0;
        __syncthreads();
        s[threadIdx.x] += t;
        __syncthreads();
    }
    if (i < N_NODES) g_row_start[i] = s[threadIdx.x] - val;  // exclusive
    if (threadIdx.x == 255) g_bsum[blockIdx.x] = s[255];
}

__global__ void scan2_kernel() {
    __shared__ int s[256];
    int t = threadIdx.x;
    int val = (t < NCHUNK) ? g_bsum[t] : 0;
    s[t] = val;
    __syncthreads();
#pragma unroll
    for (int off = 1; off < 256; off <<= 1) {
        int v = (t >= off) ? s[t - off] : 0;
        __syncthreads();
        s[t] += v;
        __syncthreads();
    }
    if (t < NCHUNK) g_boff[t] = s[t] - val;  // exclusive
}

// scan3 also computes dinv (folded to save a launch)
__global__ void scan3_kernel() {
    int i = blockIdx.x * 256 + threadIdx.x;
    if (i < N_NODES) {
        g_row_start[i] += g_boff[blockIdx.x];
        g_dinv[i] = rsqrtf((float)g_deg[i]);
    }
    if (i == 0) g_row_start[N_NODES] = N_EDGES;
}

// ---------------- CSR placement (counting sort by dst) ---------------------
__global__ void place_kernel(const int* __restrict__ src,
                             const int* __restrict__ dst) {
    int e = blockIdx.x * blockDim.x + threadIdx.x;
    if (e >= N_EDGES) return;
    int s = src[e], d = dst[e];
    int pos = g_row_start[d] + atomicAdd(&g_cnt[d], 1);
    g_csr_src[pos] = s;
    g_csr_nrm[pos] = g_dinv[s] * g_dinv[d];
}

// ---------------- register-blocked SGEMM -----------------------------------
// Y[BM=128 x OUT] per block, BK=8, 8x8 micro-tile/thread.
template <int IN, int OUT, bool HASB, int SEL, bool XGLOBAL>
__global__ void sgemm_kernel(const float* __restrict__ Xin,
                             const float* __restrict__ W,
                             const float* __restrict__ bias_in) {
    constexpr int BM = 128, BK = 8, BN = OUT;
    constexpr int TX = BN / 8, NT = TX * 16;
    __shared__ float sA[BK][BM];
    __shared__ float sB[BK][BN];
    const float* X = XGLOBAL ? g_a1 : Xin;
    float*       Y = (SEL == 0) ? g_h1 : g_h2;
    const int tid = threadIdx.x;
    const int tx = tid % TX, ty = tid / TX;
    const int row0 = blockIdx.x * BM;

    float acc[8][8] = {};
    for (int kc = 0; kc < IN; kc += BK) {
#pragma unroll
        for (int v = 0; v < 256 / NT; v++) {
            int a = tid + v * NT;
            int row = a >> 1, kq = (a & 1) * 4;
            float4 val = make_float4(0.f, 0.f, 0.f, 0.f);
            if (row0 + row < N_NODES)
                val = *(const float4*)(X + (size_t)(row0 + row) * IN + kc + kq);
            if (HASB) {
                val.x += bias_in[kc + kq];     val.y += bias_in[kc + kq + 1];
                val.z += bias_in[kc + kq + 2]; val.w += bias_in[kc + kq + 3];
            }
            sA[kq + 0][row] = val.x; sA[kq + 1][row] = val.y;
            sA[kq + 2][row] = val.z; sA[kq + 3][row] = val.w;
        }
        {
            int k = tid / (BN / 4), c4 = tid % (BN / 4);
            *(float4*)&sB[k][c4 * 4] =
                *(const float4*)(W + (size_t)(kc + k) * OUT + c4 * 4);
        }
        __syncthreads();
#pragma unroll
        for (int k = 0; k < BK; k++) {
            float ra[8], rb[8];
#pragma unroll
            for (int i = 0; i < 8; i++) ra[i] = sA[k][ty * 8 + i];
#pragma unroll
            for (int j = 0; j < 8; j++) rb[j] = sB[k][tx * 8 + j];
#pragma unroll
            for (int i = 0; i < 8; i++)
#pragma unroll
                for (int j = 0; j < 8; j++) acc[i][j] += ra[i] * rb[j];
        }
        __syncthreads();
    }
#pragma unroll
    for (int i = 0; i < 8; i++) {
        int row = row0 + ty * 8 + i;
        if (row < N_NODES) {
#pragma unroll
            for (int j = 0; j < 8; j += 4) {
                float4 v = make_float4(acc[i][j], acc[i][j + 1],
                                       acc[i][j + 2], acc[i][j + 3]);
                *(float4*)(Y + (size_t)row * OUT + tx * 8 + j) = v;
            }
        }
    }
}

// ---------------- CSR gather-reduce ----------------------------------------
template <int F, int SEL>
__global__ void gather_kernel(const float* __restrict__ bias,
                              float* __restrict__ Aout) {
    constexpr int TPN = F / 4;
    const float* H = (SEL == 0) ? g_h1 : g_h2;
    float*       A = (SEL == 0) ? g_a1 : Aout;
    int g = blockIdx.x * blockDim.x + threadIdx.x;
    int node = g / TPN;
    int lane = g % TPN;
    if (node >= N_NODES) return;
    int l4 = lane * 4;

    float di = g_dinv[node];
    float sc = di * di;
    float4 hv = *(const float4*)(H + (size_t)node * F + l4);
    float4 acc = make_float4(hv.x * sc, hv.y * sc, hv.z * sc, hv.w * sc);

    int k  = g_row_start[node];
    int re = g_row_start[node + 1];
    if (k < re) {
        int s = g_csr_src[k]; float nm = g_csr_nrm[k];
        while (++k < re) {           // software-pipelined index prefetch
            int s2 = g_csr_src[k]; float nm2 = g_csr_nrm[k];
            float4 v = *(const float4*)(H + (size_t)s * F + l4);
            acc.x += v.x * nm; acc.y += v.y * nm;
            acc.z += v.z * nm; acc.w += v.w * nm;
            s = s2; nm = nm2;
        }
        float4 v = *(const float4*)(H + (size_t)s * F + l4);
        acc.x += v.x * nm; acc.y += v.y * nm;
        acc.z += v.z * nm; acc.w += v.w * nm;
    }
    if (SEL == 1) {
        acc.x += bias[l4];     acc.y += bias[l4 + 1];
        acc.z += bias[l4 + 2]; acc.w += bias[l4 + 3];
    }
    *(float4*)(A + (size_t)node * F + l4) = acc;
}

// ---------------- launch ---------------------------------------------------
extern "C" void kernel_launch(void* const* d_in, const int* in_sizes, int n_in,
                              void* d_out, int out_size) {
    const float* x   = (const float*)d_in[0];
    const int*   ei  = (const int*)d_in[1];   // int32 (JAX demotes int64)
    const float* W1  = (const float*)d_in[2];
    const float* b1  = (const float*)d_in[3];
    const float* W2  = (const float*)d_in[4];
    const float* b2  = (const float*)d_in[5];
    float*       out = (float*)d_out;

    const int* e_src = ei;
    const int* e_dst = ei + N_EDGES;
    const int  T = 256;

    // Side stream + events for graph-forked CSR build (host resources only;
    // created/destroyed per call, outside the replayed graph).
    cudaStream_t s2;
    cudaEvent_t  evFork, evJoin;
    cudaStreamCreateWithFlags(&s2, cudaStreamNonBlocking);
    cudaEventCreateWithFlags(&evFork, cudaEventDisableTiming);
    cudaEventCreateWithFlags(&evJoin, cudaEventDisableTiming);

    // fork: CSR build chain on s2, concurrent with gemm1 on main stream
    cudaEventRecord(evFork, 0);
    cudaStreamWaitEvent(s2, evFork, 0);

    init_deg_kernel<<<(N_NODES + T - 1) / T, T, 0, s2>>>();
    count_deg_kernel<<<(N_EDGES + T - 1) / T, T, 0, s2>>>(e_dst);
    scan1_kernel<<<NCHUNK, 256, 0, s2>>>();
    scan2_kernel<<<1, 256, 0, s2>>>();
    scan3_kernel<<<NCHUNK, 256, 0, s2>>>();
    place_kernel<<<(N_EDGES + T - 1) / T, T, 0, s2>>>(e_src, e_dst);
    cudaEventRecord(evJoin, s2);

    // layer 1 GEMM (independent of edges) on main stream
    sgemm_kernel<IN_CH, HID, false, 0, false>
        <<<(N_NODES + 127) / 128, (HID / 8) * 16>>>(x, W1, nullptr);

    // join: gather1 needs both gemm1 and CSR
    cudaStreamWaitEvent(0, evJoin, 0);
    gather_kernel<HID, 0>
        <<<(N_NODES * (HID / 4) + T - 1) / T, T>>>(nullptr, nullptr);

    // layer 2 (b1 folded into GEMM input, b2 added in gather epilogue)
    sgemm_kernel<HID, OUT_CH, true, 1, true>
        <<<(N_NODES + 127) / 128, (OUT_CH / 8) * 16>>>(nullptr, W2, b1);
    gather_kernel<OUT_CH, 1>
        <<<(N_NODES * (OUT_CH / 4) + T - 1) / T, T>>>(b2, out);

    cudaEventDestroy(evFork);
    cudaEventDestroy(evJoin);
    cudaStreamDestroy(s2);
}

// round 6
// speedup vs baseline: 3.3250x; 1.0849x over previous
#include <cuda_runtime.h>

#define N_NODES 50000
#define N_EDGES 800000
#define IN_CH   128
#define HID     128
#define OUT_CH  64
#define NCHUNK  ((N_NODES + 255) / 256)   // 196

// ---------------- device-global scratch ------------------------------------
__device__ float g_h1[(size_t)N_NODES * HID];      // x @ W1
__device__ float g_G [(size_t)N_NODES * OUT_CH];   // h1 @ W2
__device__ float g_h2[(size_t)N_NODES * OUT_CH];   // A*G + c
__device__ float g_c[OUT_CH];                      // b1^T @ W2
__device__ int   g_deg[N_NODES];
__device__ float g_dinv[N_NODES];
__device__ int   g_row_start[N_NODES + 1];
__device__ int   g_cnt[N_NODES];
__device__ int   g_csr_src[N_EDGES];
__device__ float g_csr_nrm[N_EDGES];
__device__ int   g_bsum[NCHUNK];
__device__ int   g_boff[NCHUNK];

// ---------------- degree ----------------------------------------------------
__global__ void init_deg_kernel() {
    int i = blockIdx.x * blockDim.x + threadIdx.x;
    if (i < N_NODES) { g_deg[i] = 1; g_cnt[i] = 0; }  // self-loop counts once
}

__global__ void count_deg_kernel(const int* __restrict__ dst) {
    int e = blockIdx.x * blockDim.x + threadIdx.x;
    if (e < N_EDGES) atomicAdd(&g_deg[dst[e]], 1);
}

// ---------------- c = b1^T @ W2  (one block, 64 threads) -------------------
__global__ void cvec_kernel(const float* __restrict__ b1,
                            const float* __restrict__ W2) {
    int j = threadIdx.x;
    float s = 0.f;
#pragma unroll 8
    for (int k = 0; k < HID; k++) s += b1[k] * W2[(size_t)k * OUT_CH + j];
    g_c[j] = s;
}

// ---------------- 3-kernel exclusive scan of edge in-degree (deg-1) --------
__global__ void scan1_kernel() {
    __shared__ int s[256];
    int i = blockIdx.x * 256 + threadIdx.x;
    int val = (i < N_NODES) ? (g_deg[i] - 1) : 0;
    s[threadIdx.x] = val;
    __syncthreads();
#pragma unroll
    for (int off = 1; off < 256; off <<= 1) {
        int t = (threadIdx.x >= off) ? s[threadIdx.x - off] : 0;
        __syncthreads();
        s[threadIdx.x] += t;
        __syncthreads();
    }
    if (i < N_NODES) g_row_start[i] = s[threadIdx.x] - val;  // exclusive
    if (threadIdx.x == 255) g_bsum[blockIdx.x] = s[255];
}

__global__ void scan2_kernel() {
    __shared__ int s[256];
    int t = threadIdx.x;
    int val = (t < NCHUNK) ? g_bsum[t] : 0;
    s[t] = val;
    __syncthreads();
#pragma unroll
    for (int off = 1; off < 256; off <<= 1) {
        int v = (t >= off) ? s[t - off] : 0;
        __syncthreads();
        s[t] += v;
        __syncthreads();
    }
    if (t < NCHUNK) g_boff[t] = s[t] - val;  // exclusive
}

// scan3 also computes dinv (folded to save a launch)
__global__ void scan3_kernel() {
    int i = blockIdx.x * 256 + threadIdx.x;
    if (i < N_NODES) {
        g_row_start[i] += g_boff[blockIdx.x];
        g_dinv[i] = rsqrtf((float)g_deg[i]);
    }
    if (i == 0) g_row_start[N_NODES] = N_EDGES;
}

// ---------------- CSR placement (counting sort by dst) ---------------------
__global__ void place_kernel(const int* __restrict__ src,
                             const int* __restrict__ dst) {
    int e = blockIdx.x * blockDim.x + threadIdx.x;
    if (e >= N_EDGES) return;
    int s = src[e], d = dst[e];
    int pos = g_row_start[d] + atomicAdd(&g_cnt[d], 1);
    g_csr_src[pos] = s;
    g_csr_nrm[pos] = g_dinv[s] * g_dinv[d];
}

// ---------------- register-blocked SGEMM -----------------------------------
// Y[BM=128 x OUT] per block, BK=8, 8x8 micro-tile/thread.
// SEL: 0 -> X=Xin, Y=g_h1 ; 1 -> X=g_h1, Y=g_G
template <int IN, int OUT, int SEL>
__global__ void sgemm_kernel(const float* __restrict__ Xin,
                             const float* __restrict__ W) {
    constexpr int BM = 128, BK = 8, BN = OUT;
    constexpr int TX = BN / 8, NT = TX * 16;
    __shared__ float sA[BK][BM];
    __shared__ float sB[BK][BN];
    const float* X = (SEL == 0) ? Xin : g_h1;
    float*       Y = (SEL == 0) ? g_h1 : g_G;
    const int tid = threadIdx.x;
    const int tx = tid % TX, ty = tid / TX;
    const int row0 = blockIdx.x * BM;

    float acc[8][8] = {};
    for (int kc = 0; kc < IN; kc += BK) {
#pragma unroll
        for (int v = 0; v < 256 / NT; v++) {
            int a = tid + v * NT;
            int row = a >> 1, kq = (a & 1) * 4;
            float4 val = make_float4(0.f, 0.f, 0.f, 0.f);
            if (row0 + row < N_NODES)
                val = *(const float4*)(X + (size_t)(row0 + row) * IN + kc + kq);
            sA[kq + 0][row] = val.x; sA[kq + 1][row] = val.y;
            sA[kq + 2][row] = val.z; sA[kq + 3][row] = val.w;
        }
        {
            int k = tid / (BN / 4), c4 = tid % (BN / 4);
            *(float4*)&sB[k][c4 * 4] =
                *(const float4*)(W + (size_t)(kc + k) * OUT + c4 * 4);
        }
        __syncthreads();
#pragma unroll
        for (int k = 0; k < BK; k++) {
            float ra[8], rb[8];
#pragma unroll
            for (int i = 0; i < 8; i++) ra[i] = sA[k][ty * 8 + i];
#pragma unroll
            for (int j = 0; j < 8; j++) rb[j] = sB[k][tx * 8 + j];
#pragma unroll
            for (int i = 0; i < 8; i++)
#pragma unroll
                for (int j = 0; j < 8; j++) acc[i][j] += ra[i] * rb[j];
        }
        __syncthreads();
    }
#pragma unroll
    for (int i = 0; i < 8; i++) {
        int row = row0 + ty * 8 + i;
        if (row < N_NODES) {
#pragma unroll
            for (int j = 0; j < 8; j += 4) {
                float4 v = make_float4(acc[i][j], acc[i][j + 1],
                                       acc[i][j + 2], acc[i][j + 3]);
                *(float4*)(Y + (size_t)row * OUT + tx * 8 + j) = v;
            }
        }
    }
}

// ---------------- CSR gather-reduce (F=64) ---------------------------------
// SEL 0: H=g_G,  A=g_h2, bias=g_c  (h2 = A*G + c)
// SEL 1: H=g_h2, A=out,  bias=b2   (out = A*h2 + b2)
template <int SEL>
__global__ void gather_kernel(const float* __restrict__ bias_in,
                              float* __restrict__ Aout) {
    constexpr int F = OUT_CH, TPN = F / 4;
    const float* H = (SEL == 0) ? g_G : g_h2;
    float*       A = (SEL == 0) ? g_h2 : Aout;
    const float* bias = (SEL == 0) ? g_c : bias_in;
    int g = blockIdx.x * blockDim.x + threadIdx.x;
    int node = g / TPN;
    int lane = g % TPN;
    if (node >= N_NODES) return;
    int l4 = lane * 4;

    float di = g_dinv[node];
    float sc = di * di;
    float4 hv = *(const float4*)(H + (size_t)node * F + l4);
    float4 acc = make_float4(hv.x * sc, hv.y * sc, hv.z * sc, hv.w * sc);

    int k  = g_row_start[node];
    int re = g_row_start[node + 1];
    if (k < re) {
        int s = g_csr_src[k]; float nm = g_csr_nrm[k];
        while (++k < re) {           // index prefetch
            int s2 = g_csr_src[k]; float nm2 = g_csr_nrm[k];
            float4 v = *(const float4*)(H + (size_t)s * F + l4);
            acc.x += v.x * nm; acc.y += v.y * nm;
            acc.z += v.z * nm; acc.w += v.w * nm;
            s = s2; nm = nm2;
        }
        float4 v = *(const float4*)(H + (size_t)s * F + l4);
        acc.x += v.x * nm; acc.y += v.y * nm;
        acc.z += v.z * nm; acc.w += v.w * nm;
    }
    acc.x += bias[l4];     acc.y += bias[l4 + 1];
    acc.z += bias[l4 + 2]; acc.w += bias[l4 + 3];
    *(float4*)(A + (size_t)node * F + l4) = acc;
}

// ---------------- launch ---------------------------------------------------
extern "C" void kernel_launch(void* const* d_in, const int* in_sizes, int n_in,
                              void* d_out, int out_size) {
    const float* x   = (const float*)d_in[0];
    const int*   ei  = (const int*)d_in[1];   // int32 (JAX demotes int64)
    const float* W1  = (const float*)d_in[2];
    const float* b1  = (const float*)d_in[3];
    const float* W2  = (const float*)d_in[4];
    const float* b2  = (const float*)d_in[5];
    float*       out = (float*)d_out;

    const int* e_src = ei;
    const int* e_dst = ei + N_EDGES;
    const int  T = 256;

    cudaStream_t s2;
    cudaEvent_t  evFork, evJoin;
    cudaStreamCreateWithFlags(&s2, cudaStreamNonBlocking);
    cudaEventCreateWithFlags(&evFork, cudaEventDisableTiming);
    cudaEventCreateWithFlags(&evJoin, cudaEventDisableTiming);

    // fork: CSR build + c-vector on s2; dense chain on main stream
    cudaEventRecord(evFork, 0);
    cudaStreamWaitEvent(s2, evFork, 0);

    init_deg_kernel<<<(N_NODES + T - 1) / T, T, 0, s2>>>();
    count_deg_kernel<<<(N_EDGES + T - 1) / T, T, 0, s2>>>(e_dst);
    cvec_kernel<<<1, OUT_CH, 0, s2>>>(b1, W2);
    scan1_kernel<<<NCHUNK, 256, 0, s2>>>();
    scan2_kernel<<<1, 256, 0, s2>>>();
    scan3_kernel<<<NCHUNK, 256, 0, s2>>>();
    place_kernel<<<(N_EDGES + T - 1) / T, T, 0, s2>>>(e_src, e_dst);
    cudaEventRecord(evJoin, s2);

    // dense chain: h1 = x@W1 ; G = h1@W2   (no CSR dependence)
    sgemm_kernel<IN_CH, HID, 0>
        <<<(N_NODES + 127) / 128, (HID / 8) * 16>>>(x, W1);
    sgemm_kernel<HID, OUT_CH, 1>
        <<<(N_NODES + 127) / 128, (OUT_CH / 8) * 16>>>(nullptr, W2);

    // join: gathers need CSR + G
    cudaStreamWaitEvent(0, evJoin, 0);
    gather_kernel<0>
        <<<(N_NODES * (OUT_CH / 4) + T - 1) / T, T>>>(nullptr, nullptr);
    gather_kernel<1>
        <<<(N_NODES * (OUT_CH / 4) + T - 1) / T, T>>>(b2, out);

    cudaEventDestroy(evFork);
    cudaEventDestroy(evJoin);
    cudaStreamDestroy(s2);
}

// round 7
// speedup vs baseline: 4.7522x; 1.4292x over previous
#include <cuda_runtime.h>

#define N_NODES 50000
#define N_EDGES 800000
#define IN_CH   128
#define HID     128
#define OUT_CH  64
#define NCHUNK  ((N_NODES + 255) / 256)   // 196

// ---------------- device-global scratch ------------------------------------
__device__ float g_W12[IN_CH * OUT_CH];            // W1 @ W2  (128x64)
__device__ float g_G [(size_t)N_NODES * OUT_CH];   // x @ W12
__device__ float g_h2[(size_t)N_NODES * OUT_CH];   // A*G + c
__device__ float g_c[OUT_CH];                      // b1^T @ W2
__device__ float g_dinv[N_NODES];
__device__ int   g_cnt[N_NODES];                   // edge in-degree (deg-1)
__device__ int   g_pos[N_NODES];                   // placement cursor
__device__ int   g_row_start[N_NODES + 1];
__device__ int   g_csr_src[N_EDGES];
__device__ float g_csr_nrm[N_EDGES];
__device__ int   g_bsum[NCHUNK];

// ---------------- zero counters --------------------------------------------
__global__ void zero_kernel() {
    int i = blockIdx.x * blockDim.x + threadIdx.x;
    if (i < N_NODES) { g_cnt[i] = 0; g_pos[i] = 0; }
}

__global__ void count_deg_kernel(const int* __restrict__ dst) {
    int e = blockIdx.x * blockDim.x + threadIdx.x;
    if (e < N_EDGES) atomicAdd(&g_cnt[dst[e]], 1);
}

// ---------------- tiny dense precomputes (weights only) --------------------
// W12[k][j] = sum_t W1[k][t]*W2[t][j];  c[j] = sum_t b1[t]*W2[t][j]
__global__ void w12_kernel(const float* __restrict__ W1,
                           const float* __restrict__ W2,
                           const float* __restrict__ b1) {
    int idx = blockIdx.x * blockDim.x + threadIdx.x;   // 0..8191
    int k = idx >> 6, j = idx & 63;
    float s = 0.f;
#pragma unroll 8
    for (int t = 0; t < HID; t++) s += W1[k * HID + t] * W2[t * OUT_CH + j];
    g_W12[idx] = s;
    if (k == 0) {
        float c = 0.f;
#pragma unroll 8
        for (int t = 0; t < HID; t++) c += b1[t] * W2[t * OUT_CH + j];
        g_c[j] = c;
    }
}

// ---------------- scan stage 1: per-chunk exclusive scan of g_cnt ----------
__global__ void scan1_kernel() {
    __shared__ int s[256];
    int i = blockIdx.x * 256 + threadIdx.x;
    int val = (i < N_NODES) ? g_cnt[i] : 0;
    s[threadIdx.x] = val;
    __syncthreads();
#pragma unroll
    for (int off = 1; off < 256; off <<= 1) {
        int t = (threadIdx.x >= off) ? s[threadIdx.x - off] : 0;
        __syncthreads();
        s[threadIdx.x] += t;
        __syncthreads();
    }
    if (i < N_NODES) g_row_start[i] = s[threadIdx.x] - val;  // exclusive
    if (threadIdx.x == 255) g_bsum[blockIdx.x] = s[255];
}

// ---------------- scan stage 2+3 merged: each block redundantly scans the
// 196 chunk sums in smem, then applies its own offset + computes dinv. ------
__global__ void scan23_kernel() {
    __shared__ int s[256];
    int t = threadIdx.x;
    int val = (t < NCHUNK) ? g_bsum[t] : 0;
    s[t] = val;
    __syncthreads();
#pragma unroll
    for (int off = 1; off < 256; off <<= 1) {
        int v = (t >= off) ? s[t - off] : 0;
        __syncthreads();
        s[t] += v;
        __syncthreads();
    }
    __shared__ int chunk_off;
    if (t == (int)blockIdx.x) chunk_off = s[t] - val;  // exclusive offset
    __syncthreads();

    int i = blockIdx.x * 256 + t;
    if (i < N_NODES) {
        g_row_start[i] += chunk_off;
        g_dinv[i] = rsqrtf((float)(g_cnt[i] + 1));  // deg = cnt + self-loop
    }
    if (i == 0) g_row_start[N_NODES] = N_EDGES;
}

// ---------------- CSR placement (counting sort by dst) ---------------------
__global__ void place_kernel(const int* __restrict__ src,
                             const int* __restrict__ dst) {
    int e = blockIdx.x * blockDim.x + threadIdx.x;
    if (e >= N_EDGES) return;
    int s = src[e], d = dst[e];
    int pos = g_row_start[d] + atomicAdd(&g_pos[d], 1);
    g_csr_src[pos] = s;
    g_csr_nrm[pos] = g_dinv[s] * g_dinv[d];
}

// ---------------- SGEMM: G[50000x64] = x[50000x128] @ W12 ------------------
// BM=128, BK=8, BN=64, 128 threads, 8x8 micro-tile.
__global__ void gemmG_kernel(const float* __restrict__ X) {
    constexpr int BM = 128, BK = 8, BN = OUT_CH;
    constexpr int TX = BN / 8;            // 8
    __shared__ float sA[BK][BM];
    __shared__ float sB[BK][BN];
    const int tid = threadIdx.x;          // 128 threads
    const int tx = tid % TX, ty = tid / TX;
    const int row0 = blockIdx.x * BM;

    float acc[8][8] = {};
    for (int kc = 0; kc < IN_CH; kc += BK) {
#pragma unroll
        for (int v = 0; v < 2; v++) {     // 256 float4 over 128 threads
            int a = tid + v * 128;
            int row = a >> 1, kq = (a & 1) * 4;
            float4 val = make_float4(0.f, 0.f, 0.f, 0.f);
            if (row0 + row < N_NODES)
                val = *(const float4*)(X + (size_t)(row0 + row) * IN_CH + kc + kq);
            sA[kq + 0][row] = val.x; sA[kq + 1][row] = val.y;
            sA[kq + 2][row] = val.z; sA[kq + 3][row] = val.w;
        }
        {
            int k = tid >> 4, c4 = tid & 15;   // 8k x 16 float4 = 128
            *(float4*)&sB[k][c4 * 4] =
                *(const float4*)(g_W12 + (size_t)(kc + k) * OUT_CH + c4 * 4);
        }
        __syncthreads();
#pragma unroll
        for (int k = 0; k < BK; k++) {
            float ra[8], rb[8];
#pragma unroll
            for (int i = 0; i < 8; i++) ra[i] = sA[k][ty * 8 + i];
#pragma unroll
            for (int j = 0; j < 8; j++) rb[j] = sB[k][tx * 8 + j];
#pragma unroll
            for (int i = 0; i < 8; i++)
#pragma unroll
                for (int j = 0; j < 8; j++) acc[i][j] += ra[i] * rb[j];
        }
        __syncthreads();
    }
#pragma unroll
    for (int i = 0; i < 8; i++) {
        int row = row0 + ty * 8 + i;
        if (row < N_NODES) {
#pragma unroll
            for (int j = 0; j < 8; j += 4) {
                float4 v = make_float4(acc[i][j], acc[i][j + 1],
                                       acc[i][j + 2], acc[i][j + 3]);
                *(float4*)(g_G + (size_t)row * OUT_CH + tx * 8 + j) = v;
            }
        }
    }
}

// ---------------- CSR gather-reduce (F=64), 2-edge unrolled ----------------
// SEL 0: H=g_G,  A=g_h2, bias=g_c  (h2 = A*G + c)
// SEL 1: H=g_h2, A=out,  bias=b2   (out = A*h2 + b2)
template <int SEL>
__global__ void gather_kernel(const float* __restrict__ bias_in,
                              float* __restrict__ Aout) {
    constexpr int F = OUT_CH, TPN = F / 4;
    const float* H = (SEL == 0) ? g_G : g_h2;
    float*       A = (SEL == 0) ? g_h2 : Aout;
    const float* bias = (SEL == 0) ? g_c : bias_in;
    int g = blockIdx.x * blockDim.x + threadIdx.x;
    int node = g / TPN;
    int lane = g % TPN;
    if (node >= N_NODES) return;
    int l4 = lane * 4;

    float di = g_dinv[node];
    float sc = di * di;
    float4 hv = *(const float4*)(H + (size_t)node * F + l4);
    float4 acc = make_float4(hv.x * sc, hv.y * sc, hv.z * sc, hv.w * sc);

    int k  = g_row_start[node];
    int re = g_row_start[node + 1];
    for (; k + 1 < re; k += 2) {          // 2 independent loads in flight
        int s0 = __ldg(&g_csr_src[k]);     float n0 = __ldg(&g_csr_nrm[k]);
        int s1 = __ldg(&g_csr_src[k + 1]); float n1 = __ldg(&g_csr_nrm[k + 1]);
        float4 v0 = *(const float4*)(H + (size_t)s0 * F + l4);
        float4 v1 = *(const float4*)(H + (size_t)s1 * F + l4);
        acc.x += v0.x * n0 + v1.x * n1;
        acc.y += v0.y * n0 + v1.y * n1;
        acc.z += v0.z * n0 + v1.z * n1;
        acc.w += v0.w * n0 + v1.w * n1;
    }
    if (k < re) {
        int s = __ldg(&g_csr_src[k]); float nm = __ldg(&g_csr_nrm[k]);
        float4 v = *(const float4*)(H + (size_t)s * F + l4);
        acc.x += v.x * nm; acc.y += v.y * nm;
        acc.z += v.z * nm; acc.w += v.w * nm;
    }
    acc.x += bias[l4];     acc.y += bias[l4 + 1];
    acc.z += bias[l4 + 2]; acc.w += bias[l4 + 3];
    *(float4*)(A + (size_t)node * F + l4) = acc;
}

// ---------------- launch ---------------------------------------------------
extern "C" void kernel_launch(void* const* d_in, const int* in_sizes, int n_in,
                              void* d_out, int out_size) {
    const float* x   = (const float*)d_in[0];
    const int*   ei  = (const int*)d_in[1];   // int32 (JAX demotes int64)
    const float* W1  = (const float*)d_in[2];
    const float* b1  = (const float*)d_in[3];
    const float* W2  = (const float*)d_in[4];
    const float* b2  = (const float*)d_in[5];
    float*       out = (float*)d_out;

    const int* e_src = ei;
    const int* e_dst = ei + N_EDGES;
    const int  T = 256;

    cudaStream_t s2;
    cudaEvent_t  evFork, evJoin;
    cudaStreamCreateWithFlags(&s2, cudaStreamNonBlocking);
    cudaEventCreateWithFlags(&evFork, cudaEventDisableTiming);
    cudaEventCreateWithFlags(&evJoin, cudaEventDisableTiming);

    cudaEventRecord(evFork, 0);
    cudaStreamWaitEvent(s2, evFork, 0);

    // side stream: CSR build (zero -> count -> scan1 -> scan23 -> place)
    zero_kernel<<<(N_NODES + T - 1) / T, T, 0, s2>>>();
    count_deg_kernel<<<(N_EDGES + T - 1) / T, T, 0, s2>>>(e_dst);
    scan1_kernel<<<NCHUNK, 256, 0, s2>>>();
    scan23_kernel<<<NCHUNK, 256, 0, s2>>>();
    place_kernel<<<(N_EDGES + T - 1) / T, T, 0, s2>>>(e_src, e_dst);
    cudaEventRecord(evJoin, s2);

    // main stream: W12 = W1@W2 (+ c), then G = x @ W12
    w12_kernel<<<(IN_CH * OUT_CH) / 128, 128>>>(W1, W2, b1);
    gemmG_kernel<<<(N_NODES + 127) / 128, 128>>>(x);

    // join: gathers need CSR + dinv + G + c
    cudaStreamWaitEvent(0, evJoin, 0);
    gather_kernel<0>
        <<<(N_NODES * (OUT_CH / 4) + T - 1) / T, T>>>(nullptr, nullptr);
    gather_kernel<1>
        <<<(N_NODES * (OUT_CH / 4) + T - 1) / T, T>>>(b2, out);

    cudaEventDestroy(evFork);
    cudaEventDestroy(evJoin);
    cudaStreamDestroy(s2);
}

// round 8
// speedup vs baseline: 5.0778x; 1.0685x over previous
#include <cuda_runtime.h>

#define N_NODES 50000
#define N_EDGES 800000
#define IN_CH   128
#define HID     128
#define OUT_CH  64
#define NCHUNK  ((N_NODES + 255) / 256)   // 196

// ---------------- device-global scratch ------------------------------------
__device__ float g_W12[IN_CH * OUT_CH];            // W1 @ W2  (128x64)
__device__ float g_G  [(size_t)N_NODES * OUT_CH];  // x @ W12
__device__ float g_Gs [(size_t)N_NODES * OUT_CH];  // dinv .* G
__device__ float g_h2s[(size_t)N_NODES * OUT_CH];  // dinv .* h2
__device__ float g_c[OUT_CH];                      // b1^T @ W2
__device__ float g_dinv[N_NODES];
__device__ int   g_cnt[N_NODES];                   // edge in-degree (deg-1)
__device__ int   g_pos[N_NODES];                   // placement cursor (=row_start)
__device__ int   g_row_start[N_NODES + 1];
__device__ int   g_csr_src[N_EDGES];
__device__ int   g_bsum[NCHUNK];

// ---------------- zero counters --------------------------------------------
__global__ void zero_kernel() {
    int i = blockIdx.x * blockDim.x + threadIdx.x;
    if (i < N_NODES) g_cnt[i] = 0;
}

__global__ void count_deg_kernel(const int* __restrict__ dst) {
    int e = blockIdx.x * blockDim.x + threadIdx.x;
    if (e < N_EDGES) atomicAdd(&g_cnt[dst[e]], 1);
}

// ---------------- tiny dense precomputes (weights only) --------------------
__global__ void w12_kernel(const float* __restrict__ W1,
                           const float* __restrict__ W2,
                           const float* __restrict__ b1) {
    int idx = blockIdx.x * blockDim.x + threadIdx.x;   // 0..8191
    int k = idx >> 6, j = idx & 63;
    float s = 0.f;
#pragma unroll 8
    for (int t = 0; t < HID; t++) s += W1[k * HID + t] * W2[t * OUT_CH + j];
    g_W12[idx] = s;
    if (k == 0) {
        float c = 0.f;
#pragma unroll 8
        for (int t = 0; t < HID; t++) c += b1[t] * W2[t * OUT_CH + j];
        g_c[j] = c;
    }
}

// ---------------- scan stage 1: per-chunk exclusive scan of g_cnt ----------
__global__ void scan1_kernel() {
    __shared__ int s[256];
    int i = blockIdx.x * 256 + threadIdx.x;
    int val = (i < N_NODES) ? g_cnt[i] : 0;
    s[threadIdx.x] = val;
    __syncthreads();
#pragma unroll
    for (int off = 1; off < 256; off <<= 1) {
        int t = (threadIdx.x >= off) ? s[threadIdx.x - off] : 0;
        __syncthreads();
        s[threadIdx.x] += t;
        __syncthreads();
    }
    if (i < N_NODES) g_row_start[i] = s[threadIdx.x] - val;  // exclusive
    if (threadIdx.x == 255) g_bsum[blockIdx.x] = s[255];
}

// ---------------- scan 2+3 merged; also seeds g_pos and computes dinv ------
__global__ void scan23_kernel() {
    __shared__ int s[256];
    int t = threadIdx.x;
    int val = (t < NCHUNK) ? g_bsum[t] : 0;
    s[t] = val;
    __syncthreads();
#pragma unroll
    for (int off = 1; off < 256; off <<= 1) {
        int v = (t >= off) ? s[t - off] : 0;
        __syncthreads();
        s[t] += v;
        __syncthreads();
    }
    __shared__ int chunk_off;
    if (t == (int)blockIdx.x) chunk_off = s[t] - val;  // exclusive offset
    __syncthreads();

    int i = blockIdx.x * 256 + t;
    if (i < N_NODES) {
        int rs = g_row_start[i] + chunk_off;
        g_row_start[i] = rs;
        g_pos[i]       = rs;                         // placement cursor
        g_dinv[i] = rsqrtf((float)(g_cnt[i] + 1));   // deg = cnt + self-loop
    }
    if (i == 0) g_row_start[N_NODES] = N_EDGES;
}

// ---------------- CSR placement: src indices only --------------------------
__global__ void place_kernel(const int* __restrict__ src,
                             const int* __restrict__ dst) {
    int e = blockIdx.x * blockDim.x + threadIdx.x;
    if (e >= N_EDGES) return;
    g_csr_src[atomicAdd(&g_pos[dst[e]], 1)] = src[e];
}

// ---------------- SGEMM: G[50000x64] = x[50000x128] @ W12 ------------------
__global__ void gemmG_kernel(const float* __restrict__ X) {
    constexpr int BM = 128, BK = 8, BN = OUT_CH;
    constexpr int TX = BN / 8;            // 8
    __shared__ float sA[BK][BM];
    __shared__ float sB[BK][BN];
    const int tid = threadIdx.x;          // 128 threads
    const int tx = tid % TX, ty = tid / TX;
    const int row0 = blockIdx.x * BM;

    float acc[8][8] = {};
    for (int kc = 0; kc < IN_CH; kc += BK) {
#pragma unroll
        for (int v = 0; v < 2; v++) {
            int a = tid + v * 128;
            int row = a >> 1, kq = (a & 1) * 4;
            float4 val = make_float4(0.f, 0.f, 0.f, 0.f);
            if (row0 + row < N_NODES)
                val = *(const float4*)(X + (size_t)(row0 + row) * IN_CH + kc + kq);
            sA[kq + 0][row] = val.x; sA[kq + 1][row] = val.y;
            sA[kq + 2][row] = val.z; sA[kq + 3][row] = val.w;
        }
        {
            int k = tid >> 4, c4 = tid & 15;
            *(float4*)&sB[k][c4 * 4] =
                *(const float4*)(g_W12 + (size_t)(kc + k) * OUT_CH + c4 * 4);
        }
        __syncthreads();
#pragma unroll
        for (int k = 0; k < BK; k++) {
            float ra[8], rb[8];
#pragma unroll
            for (int i = 0; i < 8; i++) ra[i] = sA[k][ty * 8 + i];
#pragma unroll
            for (int j = 0; j < 8; j++) rb[j] = sB[k][tx * 8 + j];
#pragma unroll
            for (int i = 0; i < 8; i++)
#pragma unroll
                for (int j = 0; j < 8; j++) acc[i][j] += ra[i] * rb[j];
        }
        __syncthreads();
    }
#pragma unroll
    for (int i = 0; i < 8; i++) {
        int row = row0 + ty * 8 + i;
        if (row < N_NODES) {
#pragma unroll
            for (int j = 0; j < 8; j += 4) {
                float4 v = make_float4(acc[i][j], acc[i][j + 1],
                                       acc[i][j + 2], acc[i][j + 3]);
                *(float4*)(g_G + (size_t)row * OUT_CH + tx * 8 + j) = v;
            }
        }
    }
}

// ---------------- G' = dinv .* G (needs dinv only; overlaps place) ---------
__global__ void scaleG_kernel() {
    int t = blockIdx.x * blockDim.x + threadIdx.x;   // float4 granularity
    if (t >= N_NODES * (OUT_CH / 4)) return;
    int node = t / (OUT_CH / 4);
    float di = g_dinv[node];
    float4 v = *(const float4*)(g_G + (size_t)t * 4);
    v.x *= di; v.y *= di; v.z *= di; v.w *= di;
    *(float4*)(g_Gs + (size_t)t * 4) = v;
}

// ---------------- CSR gather: pure float4 sums, scale in epilogue ----------
// SEL 0: H=g_Gs,  out h2' = di^2*acc + di*c
// SEL 1: H=g_h2s, out     = di*acc + b2
template <int SEL>
__global__ void gather_kernel(const float* __restrict__ bias_in,
                              float* __restrict__ Aout) {
    constexpr int F = OUT_CH, TPN = F / 4;
    const float* H = (SEL == 0) ? g_Gs : g_h2s;
    float*       A = (SEL == 0) ? g_h2s : Aout;
    const float* bias = (SEL == 0) ? g_c : bias_in;
    int g = blockIdx.x * blockDim.x + threadIdx.x;
    int node = g / TPN;
    int lane = g % TPN;
    if (node >= N_NODES) return;
    int l4 = lane * 4;

    float4 acc = *(const float4*)(H + (size_t)node * F + l4);  // self term

    int k  = g_row_start[node];
    int re = g_row_start[node + 1];
    for (; k + 3 < re; k += 4) {          // 4 loads in flight
        int s0 = __ldg(&g_csr_src[k]);
        int s1 = __ldg(&g_csr_src[k + 1]);
        int s2 = __ldg(&g_csr_src[k + 2]);
        int s3 = __ldg(&g_csr_src[k + 3]);
        float4 v0 = *(const float4*)(H + (size_t)s0 * F + l4);
        float4 v1 = *(const float4*)(H + (size_t)s1 * F + l4);
        float4 v2 = *(const float4*)(H + (size_t)s2 * F + l4);
        float4 v3 = *(const float4*)(H + (size_t)s3 * F + l4);
        acc.x += (v0.x + v1.x) + (v2.x + v3.x);
        acc.y += (v0.y + v1.y) + (v2.y + v3.y);
        acc.z += (v0.z + v1.z) + (v2.z + v3.z);
        acc.w += (v0.w + v1.w) + (v2.w + v3.w);
    }
    for (; k < re; k++) {
        int s = __ldg(&g_csr_src[k]);
        float4 v = *(const float4*)(H + (size_t)s * F + l4);
        acc.x += v.x; acc.y += v.y; acc.z += v.z; acc.w += v.w;
    }

    float di = g_dinv[node];
    if (SEL == 0) {
        float sc = di * di;
        acc.x = sc * acc.x + di * bias[l4];
        acc.y = sc * acc.y + di * bias[l4 + 1];
        acc.z = sc * acc.z + di * bias[l4 + 2];
        acc.w = sc * acc.w + di * bias[l4 + 3];
    } else {
        acc.x = di * acc.x + bias[l4];
        acc.y = di * acc.y + bias[l4 + 1];
        acc.z = di * acc.z + bias[l4 + 2];
        acc.w = di * acc.w + bias[l4 + 3];
    }
    *(float4*)(A + (size_t)node * F + l4) = acc;
}

// ---------------- launch ---------------------------------------------------
extern "C" void kernel_launch(void* const* d_in, const int* in_sizes, int n_in,
                              void* d_out, int out_size) {
    const float* x   = (const float*)d_in[0];
    const int*   ei  = (const int*)d_in[1];   // int32 (JAX demotes int64)
    const float* W1  = (const float*)d_in[2];
    const float* b1  = (const float*)d_in[3];
    const float* W2  = (const float*)d_in[4];
    const float* b2  = (const float*)d_in[5];
    float*       out = (float*)d_out;

    const int* e_src = ei;
    const int* e_dst = ei + N_EDGES;
    const int  T = 256;

    cudaStream_t s2;
    cudaEvent_t  evFork, evDinv, evJoin;
    cudaStreamCreateWithFlags(&s2, cudaStreamNonBlocking);
    cudaEventCreateWithFlags(&evFork, cudaEventDisableTiming);
    cudaEventCreateWithFlags(&evDinv, cudaEventDisableTiming);
    cudaEventCreateWithFlags(&evJoin, cudaEventDisableTiming);

    cudaEventRecord(evFork, 0);
    cudaStreamWaitEvent(s2, evFork, 0);

    // side stream: CSR build
    zero_kernel<<<(N_NODES + T - 1) / T, T, 0, s2>>>();
    count_deg_kernel<<<(N_EDGES + T - 1) / T, T, 0, s2>>>(e_dst);
    scan1_kernel<<<NCHUNK, 256, 0, s2>>>();
    scan23_kernel<<<NCHUNK, 256, 0, s2>>>();
    cudaEventRecord(evDinv, s2);               // dinv + row_start ready
    place_kernel<<<(N_EDGES + T - 1) / T, T, 0, s2>>>(e_src, e_dst);
    cudaEventRecord(evJoin, s2);

    // main stream: W12 -> G; then G' (needs dinv, overlaps place)
    w12_kernel<<<(IN_CH * OUT_CH) / 128, 128>>>(W1, W2, b1);
    gemmG_kernel<<<(N_NODES + 127) / 128, 128>>>(x);
    cudaStreamWaitEvent(0, evDinv, 0);
    scaleG_kernel<<<(N_NODES * (OUT_CH / 4) + T - 1) / T, T>>>();

    // join: gathers need full CSR
    cudaStreamWaitEvent(0, evJoin, 0);
    gather_kernel<0>
        <<<(N_NODES * (OUT_CH / 4) + T - 1) / T, T>>>(nullptr, nullptr);
    gather_kernel<1>
        <<<(N_NODES * (OUT_CH / 4) + T - 1) / T, T>>>(b2, out);

    cudaEventDestroy(evFork);
    cudaEventDestroy(evDinv);
    cudaEventDestroy(evJoin);
    cudaStreamDestroy(s2);
}

// round 9
// speedup vs baseline: 5.1965x; 1.0234x over previous
#include <cuda_runtime.h>

#define N_NODES 50000
#define N_EDGES 800000
#define IN_CH   128
#define HID     128
#define OUT_CH  64
#define NCHUNK  ((N_NODES + 255) / 256)   // 196

// ---------------- device-global scratch ------------------------------------
__device__ float g_W12[IN_CH * OUT_CH];            // W1 @ W2  (128x64)
__device__ float g_G  [(size_t)N_NODES * OUT_CH];  // x @ W12
__device__ float g_Gs [(size_t)N_NODES * OUT_CH];  // dinv .* G
__device__ float g_h2s[(size_t)N_NODES * OUT_CH];  // dinv .* h2
__device__ float g_c[OUT_CH];                      // b1^T @ W2
__device__ float g_dinv[N_NODES];
__device__ int   g_cnt[N_NODES];                   // edge in-degree (deg-1)
__device__ int   g_pos[N_NODES];                   // placement cursor (=row_start)
__device__ int   g_row_start[N_NODES + 1];
__device__ int   g_csr_src[N_EDGES];
__device__ int   g_agg[NCHUNK];                    // chunk aggregates
__device__ volatile int g_flag[NCHUNK];            // publish flags (re-zeroed)

// ---------------- zero counters + scan flags --------------------------------
__global__ void zero_kernel() {
    int i = blockIdx.x * blockDim.x + threadIdx.x;
    if (i < N_NODES) g_cnt[i] = 0;
    if (i < NCHUNK)  g_flag[i] = 0;
}

__global__ void count_deg_kernel(const int* __restrict__ dst) {
    int e = blockIdx.x * blockDim.x + threadIdx.x;
    if (e < N_EDGES) atomicAdd(&g_cnt[dst[e]], 1);
}

// ---------------- tiny dense precomputes (weights only) --------------------
__global__ void w12_kernel(const float* __restrict__ W1,
                           const float* __restrict__ W2,
                           const float* __restrict__ b1) {
    int idx = blockIdx.x * blockDim.x + threadIdx.x;   // 0..8191
    int k = idx >> 6, j = idx & 63;
    float s = 0.f;
#pragma unroll 8
    for (int t = 0; t < HID; t++) s += W1[k * HID + t] * W2[t * OUT_CH + j];
    g_W12[idx] = s;
    if (k == 0) {
        float c = 0.f;
#pragma unroll 8
        for (int t = 0; t < HID; t++) c += b1[t] * W2[t * OUT_CH + j];
        g_c[j] = c;
    }
}

// ---------------- fused single-pass scan ------------------------------------
// Per block: local inclusive scan of its 256 g_cnt values; publish aggregate
// (flag=1); spin-wait on ALL predecessor aggregates (depth-1, no chain);
// reduce them to the chunk offset; emit row_start, pos, dinv.
// All 196 blocks co-resident (148 SMs, 8+ blocks/SM) => no deadlock.
__global__ void scan_fused_kernel() {
    __shared__ int s[256];
    __shared__ int pre[256];
    const int tid = threadIdx.x;
    const int chunk = blockIdx.x;
    const int i = chunk * 256 + tid;

    int val = (i < N_NODES) ? g_cnt[i] : 0;
    s[tid] = val;
    __syncthreads();
#pragma unroll
    for (int off = 1; off < 256; off <<= 1) {
        int t = (tid >= off) ? s[tid - off] : 0;
        __syncthreads();
        s[tid] += t;
        __syncthreads();
    }
    int incl = s[tid];

    // publish this chunk's aggregate
    if (tid == 0) {
        g_agg[chunk] = s[255];
        __threadfence();
        g_flag[chunk] = 1;
    }

    // gather predecessor aggregates (one per thread; chunk <= 195 < 256)
    int my = 0;
    if (tid < chunk) {
        while (g_flag[tid] == 0) { }       // volatile spin
        __threadfence();
        my = g_agg[tid];
    }
    __syncthreads();
    pre[tid] = my;
    __syncthreads();
#pragma unroll
    for (int off = 128; off > 0; off >>= 1) {
        if (tid < off) pre[tid] += pre[tid + off];
        __syncthreads();
    }
    int chunk_off = pre[0];

    if (i < N_NODES) {
        int rs = chunk_off + incl - val;             // exclusive scan
        g_row_start[i] = rs;
        g_pos[i]       = rs;                         // placement cursor
        g_dinv[i] = rsqrtf((float)(val + 1));        // deg = cnt + self-loop
    }
    if (i == 0) g_row_start[N_NODES] = N_EDGES;
}

// ---------------- CSR placement: src indices only --------------------------
__global__ void place_kernel(const int* __restrict__ src,
                             const int* __restrict__ dst) {
    int e = blockIdx.x * blockDim.x + threadIdx.x;
    if (e >= N_EDGES) return;
    g_csr_src[atomicAdd(&g_pos[dst[e]], 1)] = src[e];
}

// ---------------- SGEMM: G[50000x64] = x[50000x128] @ W12 ------------------
__global__ void gemmG_kernel(const float* __restrict__ X) {
    constexpr int BM = 128, BK = 8, BN = OUT_CH;
    constexpr int TX = BN / 8;            // 8
    __shared__ float sA[BK][BM];
    __shared__ float sB[BK][BN];
    const int tid = threadIdx.x;          // 128 threads
    const int tx = tid % TX, ty = tid / TX;
    const int row0 = blockIdx.x * BM;

    float acc[8][8] = {};
    for (int kc = 0; kc < IN_CH; kc += BK) {
#pragma unroll
        for (int v = 0; v < 2; v++) {
            int a = tid + v * 128;
            int row = a >> 1, kq = (a & 1) * 4;
            float4 val = make_float4(0.f, 0.f, 0.f, 0.f);
            if (row0 + row < N_NODES)
                val = *(const float4*)(X + (size_t)(row0 + row) * IN_CH + kc + kq);
            sA[kq + 0][row] = val.x; sA[kq + 1][row] = val.y;
            sA[kq + 2][row] = val.z; sA[kq + 3][row] = val.w;
        }
        {
            int k = tid >> 4, c4 = tid & 15;
            *(float4*)&sB[k][c4 * 4] =
                *(const float4*)(g_W12 + (size_t)(kc + k) * OUT_CH + c4 * 4);
        }
        __syncthreads();
#pragma unroll
        for (int k = 0; k < BK; k++) {
            float ra[8], rb[8];
#pragma unroll
            for (int i = 0; i < 8; i++) ra[i] = sA[k][ty * 8 + i];
#pragma unroll
            for (int j = 0; j < 8; j++) rb[j] = sB[k][tx * 8 + j];
#pragma unroll
            for (int i = 0; i < 8; i++)
#pragma unroll
                for (int j = 0; j < 8; j++) acc[i][j] += ra[i] * rb[j];
        }
        __syncthreads();
    }
#pragma unroll
    for (int i = 0; i < 8; i++) {
        int row = row0 + ty * 8 + i;
        if (row < N_NODES) {
#pragma unroll
            for (int j = 0; j < 8; j += 4) {
                float4 v = make_float4(acc[i][j], acc[i][j + 1],
                                       acc[i][j + 2], acc[i][j + 3]);
                *(float4*)(g_G + (size_t)row * OUT_CH + tx * 8 + j) = v;
            }
        }
    }
}

// ---------------- G' = dinv .* G (needs dinv only; overlaps place) ---------
__global__ void scaleG_kernel() {
    int t = blockIdx.x * blockDim.x + threadIdx.x;   // float4 granularity
    if (t >= N_NODES * (OUT_CH / 4)) return;
    int node = t / (OUT_CH / 4);
    float di = g_dinv[node];
    float4 v = *(const float4*)(g_G + (size_t)t * 4);
    v.x *= di; v.y *= di; v.z *= di; v.w *= di;
    *(float4*)(g_Gs + (size_t)t * 4) = v;
}

// ---------------- CSR gather: pure float4 sums, 8 loads in flight ----------
// SEL 0: H=g_Gs,  out h2' = di^2*acc + di*c
// SEL 1: H=g_h2s, out     = di*acc + b2
template <int SEL>
__global__ void gather_kernel(const float* __restrict__ bias_in,
                              float* __restrict__ Aout) {
    constexpr int F = OUT_CH, TPN = F / 4;
    const float* H = (SEL == 0) ? g_Gs : g_h2s;
    float*       A = (SEL == 0) ? g_h2s : Aout;
    const float* bias = (SEL == 0) ? g_c : bias_in;
    int g = blockIdx.x * blockDim.x + threadIdx.x;
    int node = g / TPN;
    int lane = g % TPN;
    if (node >= N_NODES) return;
    int l4 = lane * 4;

    float4 acc = *(const float4*)(H + (size_t)node * F + l4);  // self term

    int k  = g_row_start[node];
    int re = g_row_start[node + 1];
    for (; k + 7 < re; k += 8) {          // 8 independent loads in flight
        int s0 = __ldg(&g_csr_src[k]);
        int s1 = __ldg(&g_csr_src[k + 1]);
        int s2 = __ldg(&g_csr_src[k + 2]);
        int s3 = __ldg(&g_csr_src[k + 3]);
        int s4 = __ldg(&g_csr_src[k + 4]);
        int s5 = __ldg(&g_csr_src[k + 5]);
        int s6 = __ldg(&g_csr_src[k + 6]);
        int s7 = __ldg(&g_csr_src[k + 7]);
        float4 v0 = *(const float4*)(H + (size_t)s0 * F + l4);
        float4 v1 = *(const float4*)(H + (size_t)s1 * F + l4);
        float4 v2 = *(const float4*)(H + (size_t)s2 * F + l4);
        float4 v3 = *(const float4*)(H + (size_t)s3 * F + l4);
        float4 v4 = *(const float4*)(H + (size_t)s4 * F + l4);
        float4 v5 = *(const float4*)(H + (size_t)s5 * F + l4);
        float4 v6 = *(const float4*)(H + (size_t)s6 * F + l4);
        float4 v7 = *(const float4*)(H + (size_t)s7 * F + l4);
        acc.x += ((v0.x + v1.x) + (v2.x + v3.x)) + ((v4.x + v5.x) + (v6.x + v7.x));
        acc.y += ((v0.y + v1.y) + (v2.y + v3.y)) + ((v4.y + v5.y) + (v6.y + v7.y));
        acc.z += ((v0.z + v1.z) + (v2.z + v3.z)) + ((v4.z + v5.z) + (v6.z + v7.z));
        acc.w += ((v0.w + v1.w) + (v2.w + v3.w)) + ((v4.w + v5.w) + (v6.w + v7.w));
    }
    for (; k + 1 < re; k += 2) {
        int s0 = __ldg(&g_csr_src[k]);
        int s1 = __ldg(&g_csr_src[k + 1]);
        float4 v0 = *(const float4*)(H + (size_t)s0 * F + l4);
        float4 v1 = *(const float4*)(H + (size_t)s1 * F + l4);
        acc.x += v0.x + v1.x; acc.y += v0.y + v1.y;
        acc.z += v0.z + v1.z; acc.w += v0.w + v1.w;
    }
    if (k < re) {
        int s = __ldg(&g_csr_src[k]);
        float4 v = *(const float4*)(H + (size_t)s * F + l4);
        acc.x += v.x; acc.y += v.y; acc.z += v.z; acc.w += v.w;
    }

    float di = g_dinv[node];
    if (SEL == 0) {
        float sc = di * di;
        acc.x = sc * acc.x + di * bias[l4];
        acc.y = sc * acc.y + di * bias[l4 + 1];
        acc.z = sc * acc.z + di * bias[l4 + 2];
        acc.w = sc * acc.w + di * bias[l4 + 3];
    } else {
        acc.x = di * acc.x + bias[l4];
        acc.y = di * acc.y + bias[l4 + 1];
        acc.z = di * acc.z + bias[l4 + 2];
        acc.w = di * acc.w + bias[l4 + 3];
    }
    *(float4*)(A + (size_t)node * F + l4) = acc;
}

// ---------------- launch ---------------------------------------------------
extern "C" void kernel_launch(void* const* d_in, const int* in_sizes, int n_in,
                              void* d_out, int out_size) {
    const float* x   = (const float*)d_in[0];
    const int*   ei  = (const int*)d_in[1];   // int32 (JAX demotes int64)
    const float* W1  = (const float*)d_in[2];
    const float* b1  = (const float*)d_in[3];
    const float* W2  = (const float*)d_in[4];
    const float* b2  = (const float*)d_in[5];
    float*       out = (float*)d_out;

    const int* e_src = ei;
    const int* e_dst = ei + N_EDGES;
    const int  T = 256;

    cudaStream_t s2;
    cudaEvent_t  evFork, evDinv, evJoin;
    cudaStreamCreateWithFlags(&s2, cudaStreamNonBlocking);
    cudaEventCreateWithFlags(&evFork, cudaEventDisableTiming);
    cudaEventCreateWithFlags(&evDinv, cudaEventDisableTiming);
    cudaEventCreateWithFlags(&evJoin, cudaEventDisableTiming);

    cudaEventRecord(evFork, 0);
    cudaStreamWaitEvent(s2, evFork, 0);

    // side stream: CSR build (zero -> count -> fused scan -> place)
    zero_kernel<<<(N_NODES + T - 1) / T, T, 0, s2>>>();
    count_deg_kernel<<<(N_EDGES + T - 1) / T, T, 0, s2>>>(e_dst);
    scan_fused_kernel<<<NCHUNK, 256, 0, s2>>>();
    cudaEventRecord(evDinv, s2);               // dinv + row_start ready
    place_kernel<<<(N_EDGES + T - 1) / T, T, 0, s2>>>(e_src, e_dst);
    cudaEventRecord(evJoin, s2);

    // main stream: W12 -> G; then G' (needs dinv, overlaps place)
    w12_kernel<<<(IN_CH * OUT_CH) / 128, 128>>>(W1, W2, b1);
    gemmG_kernel<<<(N_NODES + 127) / 128, 128>>>(x);
    cudaStreamWaitEvent(0, evDinv, 0);
    scaleG_kernel<<<(N_NODES * (OUT_CH / 4) + T - 1) / T, T>>>();

    // join: gathers need full CSR
    cudaStreamWaitEvent(0, evJoin, 0);
    gather_kernel<0>
        <<<(N_NODES * (OUT_CH / 4) + T - 1) / T, T>>>(nullptr, nullptr);
    gather_kernel<1>
        <<<(N_NODES * (OUT_CH / 4) + T - 1) / T, T>>>(b2, out);

    cudaEventDestroy(evFork);
    cudaEventDestroy(evDinv);
    cudaEventDestroy(evJoin);
    cudaStreamDestroy(s2);
}

// round 10
// speedup vs baseline: 5.6614x; 1.0895x over previous
#include <cuda_runtime.h>
#include <cuda_fp16.h>

#define N_NODES 50000
#define N_EDGES 800000
#define IN_CH   128
#define HID     128
#define OUT_CH  64
#define NCHUNK  ((N_NODES + 255) / 256)   // 196

// ---------------- device-global scratch ------------------------------------
__device__ float  g_W12[IN_CH * OUT_CH];            // W1 @ W2  (128x64)
__device__ float  g_G  [(size_t)N_NODES * OUT_CH];  // x @ W12
__device__ __half g_Gsh[(size_t)N_NODES * OUT_CH];  // fp16(dinv .* G)
__device__ float  g_h2s[(size_t)N_NODES * OUT_CH];  // dinv .* h2
__device__ float  g_c[OUT_CH];                      // b1^T @ W2
__device__ float  g_dinv[N_NODES];
__device__ int    g_cnt[N_NODES];                   // edge in-degree (self-cleaning)
__device__ int    g_pos[N_NODES];                   // placement cursor (=row_start)
__device__ int    g_row_start[N_NODES + 1];
__device__ int    g_csr_src[N_EDGES];
__device__ int    g_agg[NCHUNK];                    // chunk aggregates
__device__ volatile int g_flag[NCHUNK];             // publish flags (cleared in count)

// ---------------- count: 4 edges/thread; block 0 clears scan flags ----------
__global__ void count_deg_kernel(const int* __restrict__ dst) {
    int t = blockIdx.x * blockDim.x + threadIdx.x;
    if (blockIdx.x == 0 && threadIdx.x < NCHUNK) g_flag[threadIdx.x] = 0;
    if (t < N_EDGES / 4) {
        int4 d = *(const int4*)(dst + t * 4);
        atomicAdd(&g_cnt[d.x], 1);
        atomicAdd(&g_cnt[d.y], 1);
        atomicAdd(&g_cnt[d.z], 1);
        atomicAdd(&g_cnt[d.w], 1);
    }
}

// ---------------- tiny dense precomputes (weights only) --------------------
__global__ void w12_kernel(const float* __restrict__ W1,
                           const float* __restrict__ W2,
                           const float* __restrict__ b1) {
    int idx = blockIdx.x * blockDim.x + threadIdx.x;   // 0..8191
    int k = idx >> 6, j = idx & 63;
    float s = 0.f;
#pragma unroll 8
    for (int t = 0; t < HID; t++) s += W1[k * HID + t] * W2[t * OUT_CH + j];
    g_W12[idx] = s;
    if (k == 0) {
        float c = 0.f;
#pragma unroll 8
        for (int t = 0; t < HID; t++) c += b1[t] * W2[t * OUT_CH + j];
        g_c[j] = c;
    }
}

// ---------------- fused single-pass scan (publish-all, wait-all) -----------
// Also self-cleans g_cnt for the next graph replay.
__global__ void scan_fused_kernel() {
    __shared__ int s[256];
    __shared__ int pre[256];
    const int tid = threadIdx.x;
    const int chunk = blockIdx.x;
    const int i = chunk * 256 + tid;

    int val = (i < N_NODES) ? g_cnt[i] : 0;
    if (i < N_NODES) g_cnt[i] = 0;        // self-clean for next replay
    s[tid] = val;
    __syncthreads();
#pragma unroll
    for (int off = 1; off < 256; off <<= 1) {
        int t = (tid >= off) ? s[tid - off] : 0;
        __syncthreads();
        s[tid] += t;
        __syncthreads();
    }
    int incl = s[tid];

    if (tid == 0) {                        // publish aggregate
        g_agg[chunk] = s[255];
        __threadfence();
        g_flag[chunk] = 1;
    }

    int my = 0;
    if (tid < chunk) {                     // depth-1 wait on predecessors
        while (g_flag[tid] == 0) { }
        __threadfence();
        my = g_agg[tid];
    }
    __syncthreads();
    pre[tid] = my;
    __syncthreads();
#pragma unroll
    for (int off = 128; off > 0; off >>= 1) {
        if (tid < off) pre[tid] += pre[tid + off];
        __syncthreads();
    }
    int chunk_off = pre[0];

    if (i < N_NODES) {
        int rs = chunk_off + incl - val;             // exclusive scan
        g_row_start[i] = rs;
        g_pos[i]       = rs;                         // placement cursor
        g_dinv[i] = rsqrtf((float)(val + 1));        // deg = cnt + self-loop
    }
    if (i == 0) g_row_start[N_NODES] = N_EDGES;
}

// ---------------- CSR placement: 4 edges/thread ----------------------------
__global__ void place_kernel(const int* __restrict__ src,
                             const int* __restrict__ dst) {
    int t = blockIdx.x * blockDim.x + threadIdx.x;
    if (t >= N_EDGES / 4) return;
    int4 s = *(const int4*)(src + t * 4);
    int4 d = *(const int4*)(dst + t * 4);
    g_csr_src[atomicAdd(&g_pos[d.x], 1)] = s.x;
    g_csr_src[atomicAdd(&g_pos[d.y], 1)] = s.y;
    g_csr_src[atomicAdd(&g_pos[d.z], 1)] = s.z;
    g_csr_src[atomicAdd(&g_pos[d.w], 1)] = s.w;
}

// ---------------- SGEMM: G[50000x64] = x[50000x128] @ W12 ------------------
__global__ void gemmG_kernel(const float* __restrict__ X) {
    constexpr int BM = 128, BK = 8, BN = OUT_CH;
    constexpr int TX = BN / 8;            // 8
    __shared__ float sA[BK][BM];
    __shared__ float sB[BK][BN];
    const int tid = threadIdx.x;          // 128 threads
    const int tx = tid % TX, ty = tid / TX;
    const int row0 = blockIdx.x * BM;

    float acc[8][8] = {};
    for (int kc = 0; kc < IN_CH; kc += BK) {
#pragma unroll
        for (int v = 0; v < 2; v++) {
            int a = tid + v * 128;
            int row = a >> 1, kq = (a & 1) * 4;
            float4 val = make_float4(0.f, 0.f, 0.f, 0.f);
            if (row0 + row < N_NODES)
                val = *(const float4*)(X + (size_t)(row0 + row) * IN_CH + kc + kq);
            sA[kq + 0][row] = val.x; sA[kq + 1][row] = val.y;
            sA[kq + 2][row] = val.z; sA[kq + 3][row] = val.w;
        }
        {
            int k = tid >> 4, c4 = tid & 15;
            *(float4*)&sB[k][c4 * 4] =
                *(const float4*)(g_W12 + (size_t)(kc + k) * OUT_CH + c4 * 4);
        }
        __syncthreads();
#pragma unroll
        for (int k = 0; k < BK; k++) {
            float ra[8], rb[8];
#pragma unroll
            for (int i = 0; i < 8; i++) ra[i] = sA[k][ty * 8 + i];
#pragma unroll
            for (int j = 0; j < 8; j++) rb[j] = sB[k][tx * 8 + j];
#pragma unroll
            for (int i = 0; i < 8; i++)
#pragma unroll
                for (int j = 0; j < 8; j++) acc[i][j] += ra[i] * rb[j];
        }
        __syncthreads();
    }
#pragma unroll
    for (int i = 0; i < 8; i++) {
        int row = row0 + ty * 8 + i;
        if (row < N_NODES) {
#pragma unroll
            for (int j = 0; j < 8; j += 4) {
                float4 v = make_float4(acc[i][j], acc[i][j + 1],
                                       acc[i][j + 2], acc[i][j + 3]);
                *(float4*)(g_G + (size_t)row * OUT_CH + tx * 8 + j) = v;
            }
        }
    }
}

// ---------------- Gs = fp16(dinv .* G)  (needs dinv; overlaps place) -------
__global__ void scaleG_kernel() {
    int t = blockIdx.x * blockDim.x + threadIdx.x;   // 4-feature granularity
    if (t >= N_NODES * (OUT_CH / 4)) return;
    int node = t / (OUT_CH / 4);
    float di = g_dinv[node];
    float4 v = *(const float4*)(g_G + (size_t)t * 4);
    __half2 lo = __floats2half2_rn(v.x * di, v.y * di);
    __half2 hi = __floats2half2_rn(v.z * di, v.w * di);
    *(__half2*)(g_Gsh + (size_t)t * 4)     = lo;
    *(__half2*)(g_Gsh + (size_t)t * 4 + 2) = hi;
}

__device__ __forceinline__ float4 ld4h(const __half* p) {
    __half2 a = ((const __half2*)p)[0];
    __half2 b = ((const __half2*)p)[1];
    float2 fa = __half22float2(a), fb = __half22float2(b);
    return make_float4(fa.x, fa.y, fb.x, fb.y);
}

// ---------------- gather0: fp16 input, fp32 accumulate ---------------------
// h2s = di^2 * (sum Gsh[nbr] + Gsh[self]) + di*c
__global__ void gather0_kernel() {
    constexpr int F = OUT_CH, TPN = F / 4;
    int g = blockIdx.x * blockDim.x + threadIdx.x;
    int node = g / TPN;
    int lane = g % TPN;
    if (node >= N_NODES) return;
    int l4 = lane * 4;
    const __half* H = g_Gsh;

    float4 acc = ld4h(H + (size_t)node * F + l4);    // self term

    int k  = g_row_start[node];
    int re = g_row_start[node + 1];
    for (; k + 7 < re; k += 8) {
        int s0 = __ldg(&g_csr_src[k]);     int s1 = __ldg(&g_csr_src[k + 1]);
        int s2 = __ldg(&g_csr_src[k + 2]); int s3 = __ldg(&g_csr_src[k + 3]);
        int s4 = __ldg(&g_csr_src[k + 4]); int s5 = __ldg(&g_csr_src[k + 5]);
        int s6 = __ldg(&g_csr_src[k + 6]); int s7 = __ldg(&g_csr_src[k + 7]);
        float4 v0 = ld4h(H + (size_t)s0 * F + l4);
        float4 v1 = ld4h(H + (size_t)s1 * F + l4);
        float4 v2 = ld4h(H + (size_t)s2 * F + l4);
        float4 v3 = ld4h(H + (size_t)s3 * F + l4);
        float4 v4 = ld4h(H + (size_t)s4 * F + l4);
        float4 v5 = ld4h(H + (size_t)s5 * F + l4);
        float4 v6 = ld4h(H + (size_t)s6 * F + l4);
        float4 v7 = ld4h(H + (size_t)s7 * F + l4);
        acc.x += ((v0.x + v1.x) + (v2.x + v3.x)) + ((v4.x + v5.x) + (v6.x + v7.x));
        acc.y += ((v0.y + v1.y) + (v2.y + v3.y)) + ((v4.y + v5.y) + (v6.y + v7.y));
        acc.z += ((v0.z + v1.z) + (v2.z + v3.z)) + ((v4.z + v5.z) + (v6.z + v7.z));
        acc.w += ((v0.w + v1.w) + (v2.w + v3.w)) + ((v4.w + v5.w) + (v6.w + v7.w));
    }
    for (; k < re; k++) {
        int s = __ldg(&g_csr_src[k]);
        float4 v = ld4h(H + (size_t)s * F + l4);
        acc.x += v.x; acc.y += v.y; acc.z += v.z; acc.w += v.w;
    }

    float di = g_dinv[node];
    float sc = di * di;
    acc.x = sc * acc.x + di * g_c[l4];
    acc.y = sc * acc.y + di * g_c[l4 + 1];
    acc.z = sc * acc.z + di * g_c[l4 + 2];
    acc.w = sc * acc.w + di * g_c[l4 + 3];
    *(float4*)(g_h2s + (size_t)node * F + l4) = acc;
}

// ---------------- gather1: fp32 throughout ---------------------------------
// out = di * (sum h2s[nbr] + h2s[self]) + b2
__global__ void gather1_kernel(const float* __restrict__ b2,
                               float* __restrict__ Aout) {
    constexpr int F = OUT_CH, TPN = F / 4;
    int g = blockIdx.x * blockDim.x + threadIdx.x;
    int node = g / TPN;
    int lane = g % TPN;
    if (node >= N_NODES) return;
    int l4 = lane * 4;
    const float* H = g_h2s;

    float4 acc = *(const float4*)(H + (size_t)node * F + l4);

    int k  = g_row_start[node];
    int re = g_row_start[node + 1];
    for (; k + 7 < re; k += 8) {
        int s0 = __ldg(&g_csr_src[k]);     int s1 = __ldg(&g_csr_src[k + 1]);
        int s2 = __ldg(&g_csr_src[k + 2]); int s3 = __ldg(&g_csr_src[k + 3]);
        int s4 = __ldg(&g_csr_src[k + 4]); int s5 = __ldg(&g_csr_src[k + 5]);
        int s6 = __ldg(&g_csr_src[k + 6]); int s7 = __ldg(&g_csr_src[k + 7]);
        float4 v0 = *(const float4*)(H + (size_t)s0 * F + l4);
        float4 v1 = *(const float4*)(H + (size_t)s1 * F + l4);
        float4 v2 = *(const float4*)(H + (size_t)s2 * F + l4);
        float4 v3 = *(const float4*)(H + (size_t)s3 * F + l4);
        float4 v4 = *(const float4*)(H + (size_t)s4 * F + l4);
        float4 v5 = *(const float4*)(H + (size_t)s5 * F + l4);
        float4 v6 = *(const float4*)(H + (size_t)s6 * F + l4);
        float4 v7 = *(const float4*)(H + (size_t)s7 * F + l4);
        acc.x += ((v0.x + v1.x) + (v2.x + v3.x)) + ((v4.x + v5.x) + (v6.x + v7.x));
        acc.y += ((v0.y + v1.y) + (v2.y + v3.y)) + ((v4.y + v5.y) + (v6.y + v7.y));
        acc.z += ((v0.z + v1.z) + (v2.z + v3.z)) + ((v4.z + v5.z) + (v6.z + v7.z));
        acc.w += ((v0.w + v1.w) + (v2.w + v3.w)) + ((v4.w + v5.w) + (v6.w + v7.w));
    }
    for (; k < re; k++) {
        int s = __ldg(&g_csr_src[k]);
        float4 v = *(const float4*)(H + (size_t)s * F + l4);
        acc.x += v.x; acc.y += v.y; acc.z += v.z; acc.w += v.w;
    }

    float di = g_dinv[node];
    acc.x = di * acc.x + b2[l4];
    acc.y = di * acc.y + b2[l4 + 1];
    acc.z = di * acc.z + b2[l4 + 2];
    acc.w = di * acc.w + b2[l4 + 3];
    *(float4*)(Aout + (size_t)node * F + l4) = acc;
}

// ---------------- launch ---------------------------------------------------
extern "C" void kernel_launch(void* const* d_in, const int* in_sizes, int n_in,
                              void* d_out, int out_size) {
    const float* x   = (const float*)d_in[0];
    const int*   ei  = (const int*)d_in[1];   // int32 (JAX demotes int64)
    const float* W1  = (const float*)d_in[2];
    const float* b1  = (const float*)d_in[3];
    const float* W2  = (const float*)d_in[4];
    const float* b2  = (const float*)d_in[5];
    float*       out = (float*)d_out;

    const int* e_src = ei;
    const int* e_dst = ei + N_EDGES;
    const int  T = 256;

    cudaStream_t s2;
    cudaEvent_t  evFork, evDinv, evJoin;
    cudaStreamCreateWithFlags(&s2, cudaStreamNonBlocking);
    cudaEventCreateWithFlags(&evFork, cudaEventDisableTiming);
    cudaEventCreateWithFlags(&evDinv, cudaEventDisableTiming);
    cudaEventCreateWithFlags(&evJoin, cudaEventDisableTiming);

    cudaEventRecord(evFork, 0);
    cudaStreamWaitEvent(s2, evFork, 0);

    // side stream: CSR build (count -> fused scan -> place); g_cnt self-cleans
    count_deg_kernel<<<(N_EDGES / 4 + T - 1) / T, T, 0, s2>>>(e_dst);
    scan_fused_kernel<<<NCHUNK, 256, 0, s2>>>();
    cudaEventRecord(evDinv, s2);               // dinv + row_start ready
    place_kernel<<<(N_EDGES / 4 + T - 1) / T, T, 0, s2>>>(e_src, e_dst);
    cudaEventRecord(evJoin, s2);

    // main stream: W12 -> G; then Gs=fp16(dinv.*G) (overlaps place)
    w12_kernel<<<(IN_CH * OUT_CH) / 128, 128>>>(W1, W2, b1);
    gemmG_kernel<<<(N_NODES + 127) / 128, 128>>>(x);
    cudaStreamWaitEvent(0, evDinv, 0);
    scaleG_kernel<<<(N_NODES * (OUT_CH / 4) + T - 1) / T, T>>>();

    // join: gathers need full CSR
    cudaStreamWaitEvent(0, evJoin, 0);
    gather0_kernel<<<(N_NODES * (OUT_CH / 4) + T - 1) / T, T>>>();
    gather1_kernel<<<(N_NODES * (OUT_CH / 4) + T - 1) / T, T>>>(b2, out);

    cudaEventDestroy(evFork);
    cudaEventDestroy(evDinv);
    cudaEventDestroy(evJoin);
    cudaStreamDestroy(s2);
}